// round 15
// baseline (speedup 1.0000x reference)
#include <cuda_runtime.h>
#include <cuda_bf16.h>
#include <math.h>

#define BATCH 4096
#define NIN   512
#define NREP  512
#define NOUT  640
#define RW    512
#define RB    64
#define NNZ   16384

// Scratch (static device globals — allowed)
__device__ float g_t[RW];
__device__ float g_bp[NOUT];
__device__ float g_lin[BATCH * NOUT];            // lin (+bias)
__device__ float g_pre[NOUT * BATCH];            // preact, TRANSPOSED [ch][batch]
__device__ uint4 g_quad[NNZ];                    // (src*264, col*264, pf, pf)
__device__ int   g_row_start[NOUT + 1];
__device__ __nv_bfloat16 g_xh[BATCH * NIN];      // x hi/lo split
__device__ __nv_bfloat16 g_xl[BATCH * NIN];
__device__ __nv_bfloat16 g_Wph[NOUT * NIN];      // Wp hi/lo split
__device__ __nv_bfloat16 g_Wpl[NOUT * NIN];

#define K4_P 33   // f32x2 words per channel row in k4a smem

// ---------------------------------------------------------------------------
// K0: zero g_t (also keeps k3 at launch slot 4 -> ncu profiles it)
// ---------------------------------------------------------------------------
__global__ void kz(void) { g_t[threadIdx.x] = 0.0f; }

// ---------------------------------------------------------------------------
// K1: t = Qw^T @ wflat (blocks 0..1279, at DRAM roofline — FROZEN)
// Blocks 1280..1311: x -> bf16 hi/lo split (rides free under the Qw stream).
// ---------------------------------------------------------------------------
__global__ __launch_bounds__(512) void k1_qwt(const float* __restrict__ Qw,
                                              const float* __restrict__ w,
                                              const float* __restrict__ x) {
    const int tid = threadIdx.x;
    if (blockIdx.x >= 1280) {
        const int cb = blockIdx.x - 1280;                 // 0..31
        const float4* x4 = reinterpret_cast<const float4*>(x);
        uint2* xh2 = reinterpret_cast<uint2*>(g_xh);
        uint2* xl2 = reinterpret_cast<uint2*>(g_xl);
#pragma unroll 4
        for (int i = 0; i < 32; i++) {
            const int idx4 = cb * 16384 + i * 512 + tid;  // float4 index
            const float4 v = x4[idx4];
            __nv_bfloat16 h0 = __float2bfloat16_rn(v.x);
            __nv_bfloat16 h1 = __float2bfloat16_rn(v.y);
            __nv_bfloat16 h2 = __float2bfloat16_rn(v.z);
            __nv_bfloat16 h3 = __float2bfloat16_rn(v.w);
            __nv_bfloat16 l0 = __float2bfloat16_rn(v.x - __bfloat162float(h0));
            __nv_bfloat16 l1 = __float2bfloat16_rn(v.y - __bfloat162float(h1));
            __nv_bfloat16 l2 = __float2bfloat16_rn(v.z - __bfloat162float(h2));
            __nv_bfloat16 l3 = __float2bfloat16_rn(v.w - __bfloat162float(h3));
            uint2 uh, ul;
            uh.x = ((unsigned)__bfloat16_as_ushort(h1) << 16) | __bfloat16_as_ushort(h0);
            uh.y = ((unsigned)__bfloat16_as_ushort(h3) << 16) | __bfloat16_as_ushort(h2);
            ul.x = ((unsigned)__bfloat16_as_ushort(l1) << 16) | __bfloat16_as_ushort(l0);
            ul.y = ((unsigned)__bfloat16_as_ushort(l3) << 16) | __bfloat16_as_ushort(l2);
            xh2[idx4] = uh;
            xl2[idx4] = ul;
        }
        return;
    }

    __shared__ float s_w[256];
    const int rowBase = blockIdx.x * 256;
    if (tid < 256) s_w[tid] = w[rowBase + tid];
    __syncthreads();

    float acc = 0.0f;
    const float* p = Qw + (size_t)rowBase * RW + tid;
#pragma unroll 8
    for (int i = 0; i < 256; i++) {
        acc += p[(size_t)i * RW] * s_w[i];
    }
    atomicAdd(&g_t[tid], acc);
}

// ---------------------------------------------------------------------------
// K2: Wp[i] = dot(Qw[i,:], t), written as bf16 hi/lo (second Qw stream).
// Blocks 0..2559: GEMV. Block 2560: CSR sort. Block 2561: bias.
// ---------------------------------------------------------------------------
__global__ __launch_bounds__(256) void k2_wp(
    const float* __restrict__ Qw,
    const int* __restrict__ bsrc, const int* __restrict__ brow,
    const int* __restrict__ bcol, const float* __restrict__ bp_params,
    const float* __restrict__ Qb, const float* __restrict__ b) {
    const int tid = threadIdx.x;

    if (blockIdx.x >= 2560) {
        if (blockIdx.x == 2560) {
            __shared__ int c[NOUT];
            __shared__ int scan[NOUT];
            __shared__ int off[NOUT];
            for (int i = tid; i < NOUT; i += 256) c[i] = 0;
            __syncthreads();
            for (int k = tid; k < NNZ; k += 256) atomicAdd(&c[brow[k]], 1);
            __syncthreads();
            if (tid < 32) {
                int base = 0;
#pragma unroll
                for (int ch = 0; ch < NOUT / 32; ch++) {
                    int v = c[ch * 32 + tid];
#pragma unroll
                    for (int d = 1; d < 32; d <<= 1) {
                        int n = __shfl_up_sync(0xffffffffu, v, d);
                        if (tid >= d) v += n;
                    }
                    scan[ch * 32 + tid] = v + base;
                    base += __shfl_sync(0xffffffffu, v, 31);
                }
            }
            __syncthreads();
            for (int i = tid; i < NOUT; i += 256) {
                const int s = scan[i] - c[i];
                g_row_start[i] = s;
                off[i] = s;
            }
            if (tid == 0) g_row_start[NOUT] = NNZ;
            __syncthreads();
            for (int k = tid; k < NNZ; k += 256) {
                const int r = brow[k];
                const int pos = atomicAdd(&off[r], 1);
                const unsigned pf = __float_as_uint(bp_params[k]);
                g_quad[pos] = make_uint4(
                    (unsigned)(bsrc[k] * (K4_P * 8)),
                    (unsigned)(bcol[k] * (K4_P * 8)), pf, pf);
            }
        } else {
            __shared__ float s_part[4][RB];
            __shared__ float s_s[RB];
            const int r = tid & 63;
            const int chunk = tid >> 6;
            float acc = 0.0f;
            for (int i = chunk * 160; i < chunk * 160 + 160; i++)
                acc += Qb[i * RB + r] * b[i];
            s_part[chunk][r] = acc;
            __syncthreads();
            if (tid < RB) {
                s_s[tid] = s_part[0][tid] + s_part[1][tid] +
                           s_part[2][tid] + s_part[3][tid];
            }
            __syncthreads();
            for (int j = tid; j < NOUT; j += 256) {
                const float4* q4 = reinterpret_cast<const float4*>(Qb + j * RB);
                const float4* s4 = reinterpret_cast<const float4*>(s_s);
                float a = 0.0f;
#pragma unroll
                for (int u = 0; u < 16; u++) {
                    float4 q = q4[u];
                    float4 s = s4[u];
                    a += q.x * s.x + q.y * s.y + q.z * s.z + q.w * s.w;
                }
                g_bp[j] = a;
            }
        }
        return;
    }

    __shared__ float s_t[RW];
    for (int i = tid; i < RW; i += 256) s_t[i] = g_t[i];
    __syncthreads();

    const int warp = tid >> 5;
    const int lane = tid & 31;
    const int row0 = (blockIdx.x * 8 + warp) * 16;
    const float4* t4 = reinterpret_cast<const float4*>(s_t);

    for (int rr = 0; rr < 16; rr++) {
        const int row = row0 + rr;
        const float4* p4 = reinterpret_cast<const float4*>(Qw + (size_t)row * RW);
        float acc = 0.0f;
#pragma unroll
        for (int u = 0; u < 4; u++) {
            float4 q = p4[lane + 32 * u];
            float4 tt = t4[lane + 32 * u];
            acc += q.x * tt.x + q.y * tt.y + q.z * tt.z + q.w * tt.w;
        }
#pragma unroll
        for (int off = 16; off > 0; off >>= 1)
            acc += __shfl_xor_sync(0xffffffffu, acc, off);
        if (lane == 0) {
            const __nv_bfloat16 hb = __float2bfloat16_rn(acc);
            g_Wph[row] = hb;
            g_Wpl[row] = __float2bfloat16_rn(acc - __bfloat162float(hb));
        }
    }
}

// ---------------------------------------------------------------------------
// K3: lin = x @ Wp^T + bp via bf16 3-way-split tensor mma + ldmatrix.
// Block 256 thr = 8 warps (4m x 2n); block tile 128x64; warp tile 32x32.
// KP=20 -> 80B row stride: 16B-aligned rows (ldmatrix requirement) AND
// conflict-free (20k mod 32 distinct for k=0..7).
// grid (10, 32) = 320 blocks. LAUNCH #4 -> profiled.
// ---------------------------------------------------------------------------
#define KP 20   // u32 words per smem row (16 + 4 pad); row stride 80 B

__device__ __forceinline__ void mma_bf16(float* d, const unsigned* a,
                                         const unsigned* bq) {
    asm volatile(
        "mma.sync.aligned.m16n8k16.row.col.f32.bf16.bf16.f32 "
        "{%0,%1,%2,%3}, {%4,%5,%6,%7}, {%8,%9}, {%0,%1,%2,%3};"
        : "+f"(d[0]), "+f"(d[1]), "+f"(d[2]), "+f"(d[3])
        : "r"(a[0]), "r"(a[1]), "r"(a[2]), "r"(a[3]), "r"(bq[0]), "r"(bq[1]));
}

__device__ __forceinline__ void ldsm_x4(unsigned* r, unsigned addr) {
    asm volatile(
        "ldmatrix.sync.aligned.m8n8.x4.shared.b16 {%0,%1,%2,%3}, [%4];"
        : "=r"(r[0]), "=r"(r[1]), "=r"(r[2]), "=r"(r[3]) : "r"(addr));
}

__device__ __forceinline__ unsigned smem_u32(const void* p) {
    unsigned a;
    asm("{ .reg .u64 t; cvta.to.shared.u64 t, %1; cvt.u32.u64 %0, t; }"
        : "=r"(a) : "l"(p));
    return a;
}

__global__ __launch_bounds__(256) void k3_mma(void) {
    __shared__ unsigned Ah[128][KP];
    __shared__ unsigned Al[128][KP];
    __shared__ unsigned Bh[64][KP];
    __shared__ unsigned Bl[64][KP];

    const int tid  = threadIdx.x;
    const int warp = tid >> 5;
    const int lane = tid & 31;
    const int grp  = lane >> 2;
    const int tg   = lane & 3;
    const int wm = (warp >> 1) * 32;      // warp m offset within 128
    const int wn = (warp & 1) * 32;       // warp n offset within 64
    const int bn0 = blockIdx.x * 64;
    const int bm0 = blockIdx.y * 128;

    // ldmatrix lane-address components (same every kt; s adds 32 B)
    // A 16x16 tile: lanes 0-15 rows 0-15 (k quad 0), lanes 16-31 (k quad 1)
    const int aRow = wm + (lane & 15);
    const int aCq  = (lane >> 4) * 4;
    // B: lanes 0-7 n0-7/kq0, 8-15 n0-7/kq1, 16-23 n8-15/kq0, 24-31 n8-15/kq1
    const int bRow = wn + (lane & 7) + (lane >> 4) * 8;
    const int bCq  = ((lane >> 3) & 1) * 4;

    const unsigned ahA0 = smem_u32(&Ah[aRow][aCq]);
    const unsigned alA0 = smem_u32(&Al[aRow][aCq]);
    const unsigned bhA0 = smem_u32(&Bh[bRow][bCq]);
    const unsigned blA0 = smem_u32(&Bl[bRow][bCq]);

    float d[2][4][4];
#pragma unroll
    for (int mf = 0; mf < 2; mf++)
#pragma unroll
        for (int nf = 0; nf < 4; nf++)
#pragma unroll
            for (int q = 0; q < 4; q++) d[mf][nf][q] = 0.0f;

    const int brow = tid >> 2, bseg = tid & 3;   // B gmem loader

    for (int kt = 0; kt < 16; kt++) {
        const int kbase = kt * 32;   // bf16 elements
        // ---- load A (xh, xl): 2 uint4/thread/precision ----
#pragma unroll
        for (int i = 0; i < 2; i++) {
            const int idx = tid + 256 * i;
            const int row = idx >> 2;
            const int seg = idx & 3;
            const uint4 vh = *reinterpret_cast<const uint4*>(
                g_xh + (size_t)(bm0 + row) * NIN + kbase + seg * 8);
            const uint4 vl = *reinterpret_cast<const uint4*>(
                g_xl + (size_t)(bm0 + row) * NIN + kbase + seg * 8);
            Ah[row][seg * 4 + 0] = vh.x; Ah[row][seg * 4 + 1] = vh.y;
            Ah[row][seg * 4 + 2] = vh.z; Ah[row][seg * 4 + 3] = vh.w;
            Al[row][seg * 4 + 0] = vl.x; Al[row][seg * 4 + 1] = vl.y;
            Al[row][seg * 4 + 2] = vl.z; Al[row][seg * 4 + 3] = vl.w;
        }
        // ---- load B (Wph, Wpl): 1 uint4/thread/precision ----
        {
            const uint4 vh = *reinterpret_cast<const uint4*>(
                g_Wph + (size_t)(bn0 + brow) * NIN + kbase + bseg * 8);
            const uint4 vl = *reinterpret_cast<const uint4*>(
                g_Wpl + (size_t)(bn0 + brow) * NIN + kbase + bseg * 8);
            Bh[brow][bseg * 4 + 0] = vh.x; Bh[brow][bseg * 4 + 1] = vh.y;
            Bh[brow][bseg * 4 + 2] = vh.z; Bh[brow][bseg * 4 + 3] = vh.w;
            Bl[brow][bseg * 4 + 0] = vl.x; Bl[brow][bseg * 4 + 1] = vl.y;
            Bl[brow][bseg * 4 + 2] = vl.z; Bl[brow][bseg * 4 + 3] = vl.w;
        }
        __syncthreads();

#pragma unroll
        for (int s = 0; s < 2; s++) {
            const unsigned so = s * 32;   // +8 u32 cols = 32 B
            unsigned ah[2][4], al[2][4], bh[2][4], bl[2][4];
            // A fragments: mf tile at +mf*16 rows = +16*80 B
            ldsm_x4(ah[0], ahA0 + so);
            ldsm_x4(ah[1], ahA0 + so + 16 * (KP * 4));
            ldsm_x4(al[0], alA0 + so);
            ldsm_x4(al[1], alA0 + so + 16 * (KP * 4));
            // B fragments: pair p covers n +p*16 rows
            ldsm_x4(bh[0], bhA0 + so);
            ldsm_x4(bh[1], bhA0 + so + 16 * (KP * 4));
            ldsm_x4(bl[0], blA0 + so);
            ldsm_x4(bl[1], blA0 + so + 16 * (KP * 4));
#pragma unroll
            for (int mf = 0; mf < 2; mf++)
#pragma unroll
                for (int p = 0; p < 2; p++) {
                    // nf = p*2 + 0 -> words {0,1}; nf = p*2+1 -> words {2,3}
                    mma_bf16(d[mf][p * 2 + 0], ah[mf], &bh[p][0]);
                    mma_bf16(d[mf][p * 2 + 0], ah[mf], &bl[p][0]);
                    mma_bf16(d[mf][p * 2 + 0], al[mf], &bh[p][0]);
                    mma_bf16(d[mf][p * 2 + 1], ah[mf], &bh[p][2]);
                    mma_bf16(d[mf][p * 2 + 1], ah[mf], &bl[p][2]);
                    mma_bf16(d[mf][p * 2 + 1], al[mf], &bh[p][2]);
                }
        }
        __syncthreads();
    }

    // epilogue: add bias, store float2 per fragment half
#pragma unroll
    for (int nf = 0; nf < 4; nf++) {
        const int col = bn0 + wn + nf * 8 + tg * 2;
        const float2 bv = *reinterpret_cast<const float2*>(&g_bp[col]);
#pragma unroll
        for (int mf = 0; mf < 2; mf++) {
            const int row0 = bm0 + wm + mf * 16 + grp;
            float2 v0 = make_float2(d[mf][nf][0] + bv.x, d[mf][nf][1] + bv.y);
            float2 v1 = make_float2(d[mf][nf][2] + bv.x, d[mf][nf][3] + bv.y);
            *reinterpret_cast<float2*>(g_lin + (size_t)row0 * NOUT + col) = v0;
            *reinterpret_cast<float2*>(g_lin + (size_t)(row0 + 8) * NOUT + col) = v1;
        }
    }
}

// ---------------------------------------------------------------------------
// K4a: bilinear CSR -> preact; fat nnz records (pre-scaled byte offsets +
// duplicated param) cut per-nnz instruction count ~11 -> ~8.
// ---------------------------------------------------------------------------
extern __shared__ float2 k4_s2[];   // [640][33]

__global__ __launch_bounds__(512) void k4a_bilinear(void) {
    const int tid  = threadIdx.x;
    const int warp = tid >> 5;
    const int lane = tid & 31;
    const int grp  = blockIdx.x >> 1;
    const int half = blockIdx.x & 1;
    const int b0   = grp * 64;

#pragma unroll
    for (int i = 0; i < 4; i++) {
        const int bb = warp + 16 * i;
        const float* src = g_lin + (size_t)(b0 + bb) * NOUT;
        float* base = reinterpret_cast<float*>(k4_s2) + (bb & 1);
        const int pr = bb >> 1;
        for (int ch = lane; ch < NOUT; ch += 32)
            base[(ch * K4_P + pr) * 2] = src[ch];
    }
    __syncthreads();

    const char* sbase = reinterpret_cast<const char*>(k4_s2) + lane * 8;
    const unsigned long long* s_u64 =
        reinterpret_cast<const unsigned long long*>(k4_s2) + lane;
    unsigned long long c01;
    asm("mov.b64 %0, {%1, %1};" : "=l"(c01) : "f"(0.1f));

#define K4_STEP(ACC, Q)                                                       \
    {                                                                         \
        unsigned long long av = *reinterpret_cast<const unsigned long long*>( \
            sbase + (Q).x);                                                   \
        unsigned long long bv = *reinterpret_cast<const unsigned long long*>( \
            sbase + (Q).y);                                                   \
        unsigned long long pp, t;                                             \
        asm("mov.b64 %0, {%1, %2};" : "=l"(pp) : "r"((Q).z), "r"((Q).w));     \
        asm("mul.rn.f32x2 %0, %1, %2;" : "=l"(t) : "l"(av), "l"(bv));         \
        asm("fma.rn.f32x2 %0, %1, %2, %0;" : "+l"(ACC) : "l"(t), "l"(pp));    \
    }

#pragma unroll 2
    for (int i = 0; i < 20; i++) {
        const int row = half * 320 + warp + 16 * i;
        const int ks = g_row_start[row];
        const int ke = g_row_start[row + 1];
        unsigned long long a0 = 0ull, a1 = 0ull, a2c = 0ull, a3 = 0ull;
        int k = ks;
        for (; k + 3 < ke; k += 4) {
            const uint4 q0 = g_quad[k + 0];
            const uint4 q1 = g_quad[k + 1];
            const uint4 q2 = g_quad[k + 2];
            const uint4 q3 = g_quad[k + 3];
            K4_STEP(a0, q0)
            K4_STEP(a1, q1)
            K4_STEP(a2c, q2)
            K4_STEP(a3, q3)
        }
        for (; k < ke; k++) {
            const uint4 q0 = g_quad[k];
            K4_STEP(a0, q0)
        }
        unsigned long long acc;
        asm("add.rn.f32x2 %0, %1, %2;" : "=l"(acc) : "l"(a0), "l"(a1));
        asm("add.rn.f32x2 %0, %1, %2;" : "+l"(acc) : "l"(acc), "l"(a2c));
        asm("add.rn.f32x2 %0, %1, %2;" : "+l"(acc) : "l"(acc), "l"(a3));

        unsigned long long linv = s_u64[row * K4_P];
        unsigned long long pv;
        asm("mul.rn.f32x2 %0, %1, %2;" : "=l"(pv) : "l"(acc), "l"(c01));
        asm("add.rn.f32x2 %0, %1, %2;" : "+l"(pv) : "l"(pv), "l"(linv));
        *reinterpret_cast<unsigned long long*>(
            g_pre + (size_t)row * BATCH + b0 + 2 * lane) = pv;
    }
}

// ---------------------------------------------------------------------------
// K4b: gated nonlinearity from transposed preact (FROZEN, ~6us)
// ---------------------------------------------------------------------------
__global__ __launch_bounds__(256) void k4b_gate(
    const int* __restrict__ gate_idx, float* __restrict__ out) {
    __shared__ float s_t[32][257];
    const int tid = threadIdx.x;
    const int b0 = blockIdx.x * 256;
    const int j0 = blockIdx.y * 32;

#pragma unroll 4
    for (int jj = 0; jj < 32; jj++) {
        const int j = j0 + jj;
        const int gi = gate_idx[j];
        const float v = g_pre[(size_t)j * BATCH + b0 + tid];
        const float g = g_pre[(size_t)gi * BATCH + b0 + tid];
        s_t[jj][tid] = v / (1.0f + __expf(-g));
    }
    __syncthreads();

    float* dst = out + (size_t)(b0 + tid) * NREP + j0;
#pragma unroll
    for (int q = 0; q < 8; q++) {
        float4 v = make_float4(s_t[q * 4 + 0][tid], s_t[q * 4 + 1][tid],
                               s_t[q * 4 + 2][tid], s_t[q * 4 + 3][tid]);
        *reinterpret_cast<float4*>(dst + q * 4) = v;
    }
}

// ---------------------------------------------------------------------------
// Launch
// ---------------------------------------------------------------------------
extern "C" void kernel_launch(void* const* d_in, const int* in_sizes, int n_in,
                              void* d_out, int out_size) {
    const float* x        = (const float*)d_in[0];
    const float* W_weight = (const float*)d_in[1];
    const float* b        = (const float*)d_in[2];
    const float* Qw       = (const float*)d_in[3];
    const float* Qb       = (const float*)d_in[4];
    const float* bi_p     = (const float*)d_in[5];
    const int*   bi_src   = (const int*)d_in[6];
    const int*   bi_row   = (const int*)d_in[7];
    const int*   bi_col   = (const int*)d_in[8];
    const int*   gate_idx = (const int*)d_in[9];
    float* out = (float*)d_out;

    static int smem_set = 0;
    const int k4_smem_bytes = NOUT * K4_P * sizeof(float2);  // 168,960
    if (!smem_set) {
        cudaFuncSetAttribute(k4a_bilinear,
                             cudaFuncAttributeMaxDynamicSharedMemorySize,
                             k4_smem_bytes);
        smem_set = 1;
    }

    kz<<<1, 512>>>();
    k1_qwt<<<1312, 512>>>(Qw, W_weight, x);   // 1280 GEMV + 32 x-split blocks
    k2_wp<<<2562, 256>>>(Qw, bi_src, bi_row, bi_col, bi_p, Qb, b);
    k3_mma<<<dim3(NOUT / 64, BATCH / 128), 256>>>();   // launch #4 -> profiled
    k4a_bilinear<<<128, 512, k4_smem_bytes>>>();
    k4b_gate<<<dim3(BATCH / 256, NREP / 32), 256>>>(gate_idx, out);
}

// round 16
// speedup vs baseline: 1.0522x; 1.0522x over previous
#include <cuda_runtime.h>
#include <cuda_bf16.h>
#include <math.h>

#define BATCH 4096
#define NIN   512
#define NREP  512
#define NOUT  640
#define RW    512
#define RB    64
#define NNZ   16384

// Scratch (static device globals — allowed)
__device__ float g_t[RW];
__device__ float g_bp[NOUT];
__device__ float g_lin[BATCH * NOUT];            // lin (+bias)
__device__ float g_pre[NOUT * BATCH];            // preact, TRANSPOSED [ch][batch]
__device__ uint2 g_pair[NNZ];                    // (src | col<<10, bits(param))
__device__ int   g_row_start[NOUT + 1];
__device__ __nv_bfloat16 g_xh[BATCH * NIN];      // x hi/lo split
__device__ __nv_bfloat16 g_xl[BATCH * NIN];
__device__ __nv_bfloat16 g_Wph[NOUT * NIN];      // Wp hi/lo split
__device__ __nv_bfloat16 g_Wpl[NOUT * NIN];

#define K4_P 33   // f32x2 words per channel row in k4a smem

// ---------------------------------------------------------------------------
// K0: zero g_t (also keeps k3 at launch slot 4 -> ncu profiles it)
// ---------------------------------------------------------------------------
__global__ void kz(void) { g_t[threadIdx.x] = 0.0f; }

// ---------------------------------------------------------------------------
// K1: t = Qw^T @ wflat (blocks 0..1279, at DRAM roofline — FROZEN)
// Blocks 1280..1311: x -> bf16 hi/lo split (rides free under the Qw stream).
// ---------------------------------------------------------------------------
__global__ __launch_bounds__(512) void k1_qwt(const float* __restrict__ Qw,
                                              const float* __restrict__ w,
                                              const float* __restrict__ x) {
    const int tid = threadIdx.x;
    if (blockIdx.x >= 1280) {
        const int cb = blockIdx.x - 1280;                 // 0..31
        const float4* x4 = reinterpret_cast<const float4*>(x);
        uint2* xh2 = reinterpret_cast<uint2*>(g_xh);
        uint2* xl2 = reinterpret_cast<uint2*>(g_xl);
#pragma unroll 4
        for (int i = 0; i < 32; i++) {
            const int idx4 = cb * 16384 + i * 512 + tid;  // float4 index
            const float4 v = x4[idx4];
            __nv_bfloat16 h0 = __float2bfloat16_rn(v.x);
            __nv_bfloat16 h1 = __float2bfloat16_rn(v.y);
            __nv_bfloat16 h2 = __float2bfloat16_rn(v.z);
            __nv_bfloat16 h3 = __float2bfloat16_rn(v.w);
            __nv_bfloat16 l0 = __float2bfloat16_rn(v.x - __bfloat162float(h0));
            __nv_bfloat16 l1 = __float2bfloat16_rn(v.y - __bfloat162float(h1));
            __nv_bfloat16 l2 = __float2bfloat16_rn(v.z - __bfloat162float(h2));
            __nv_bfloat16 l3 = __float2bfloat16_rn(v.w - __bfloat162float(h3));
            uint2 uh, ul;
            uh.x = ((unsigned)__bfloat16_as_ushort(h1) << 16) | __bfloat16_as_ushort(h0);
            uh.y = ((unsigned)__bfloat16_as_ushort(h3) << 16) | __bfloat16_as_ushort(h2);
            ul.x = ((unsigned)__bfloat16_as_ushort(l1) << 16) | __bfloat16_as_ushort(l0);
            ul.y = ((unsigned)__bfloat16_as_ushort(l3) << 16) | __bfloat16_as_ushort(l2);
            xh2[idx4] = uh;
            xl2[idx4] = ul;
        }
        return;
    }

    __shared__ float s_w[256];
    const int rowBase = blockIdx.x * 256;
    if (tid < 256) s_w[tid] = w[rowBase + tid];
    __syncthreads();

    float acc = 0.0f;
    const float* p = Qw + (size_t)rowBase * RW + tid;
#pragma unroll 8
    for (int i = 0; i < 256; i++) {
        acc += p[(size_t)i * RW] * s_w[i];
    }
    atomicAdd(&g_t[tid], acc);
}

// ---------------------------------------------------------------------------
// K2: Wp[i] = dot(Qw[i,:], t), written as bf16 hi/lo (second Qw stream).
// Blocks 0..2559: GEMV. Block 2560: CSR sort. Block 2561: bias.
// ---------------------------------------------------------------------------
__global__ __launch_bounds__(256) void k2_wp(
    const float* __restrict__ Qw,
    const int* __restrict__ bsrc, const int* __restrict__ brow,
    const int* __restrict__ bcol, const float* __restrict__ bp_params,
    const float* __restrict__ Qb, const float* __restrict__ b) {
    const int tid = threadIdx.x;

    if (blockIdx.x >= 2560) {
        if (blockIdx.x == 2560) {
            __shared__ int c[NOUT];
            __shared__ int scan[NOUT];
            __shared__ int off[NOUT];
            for (int i = tid; i < NOUT; i += 256) c[i] = 0;
            __syncthreads();
            for (int k = tid; k < NNZ; k += 256) atomicAdd(&c[brow[k]], 1);
            __syncthreads();
            if (tid < 32) {
                int base = 0;
#pragma unroll
                for (int ch = 0; ch < NOUT / 32; ch++) {
                    int v = c[ch * 32 + tid];
#pragma unroll
                    for (int d = 1; d < 32; d <<= 1) {
                        int n = __shfl_up_sync(0xffffffffu, v, d);
                        if (tid >= d) v += n;
                    }
                    scan[ch * 32 + tid] = v + base;
                    base += __shfl_sync(0xffffffffu, v, 31);
                }
            }
            __syncthreads();
            for (int i = tid; i < NOUT; i += 256) {
                const int s = scan[i] - c[i];
                g_row_start[i] = s;
                off[i] = s;
            }
            if (tid == 0) g_row_start[NOUT] = NNZ;
            __syncthreads();
            for (int k = tid; k < NNZ; k += 256) {
                const int r = brow[k];
                const int pos = atomicAdd(&off[r], 1);
                g_pair[pos] = make_uint2(
                    (unsigned)bsrc[k] | ((unsigned)bcol[k] << 10),
                    __float_as_uint(bp_params[k]));
            }
        } else {
            __shared__ float s_part[4][RB];
            __shared__ float s_s[RB];
            const int r = tid & 63;
            const int chunk = tid >> 6;
            float acc = 0.0f;
            for (int i = chunk * 160; i < chunk * 160 + 160; i++)
                acc += Qb[i * RB + r] * b[i];
            s_part[chunk][r] = acc;
            __syncthreads();
            if (tid < RB) {
                s_s[tid] = s_part[0][tid] + s_part[1][tid] +
                           s_part[2][tid] + s_part[3][tid];
            }
            __syncthreads();
            for (int j = tid; j < NOUT; j += 256) {
                const float4* q4 = reinterpret_cast<const float4*>(Qb + j * RB);
                const float4* s4 = reinterpret_cast<const float4*>(s_s);
                float a = 0.0f;
#pragma unroll
                for (int u = 0; u < 16; u++) {
                    float4 q = q4[u];
                    float4 s = s4[u];
                    a += q.x * s.x + q.y * s.y + q.z * s.z + q.w * s.w;
                }
                g_bp[j] = a;
            }
        }
        return;
    }

    __shared__ float s_t[RW];
    for (int i = tid; i < RW; i += 256) s_t[i] = g_t[i];
    __syncthreads();

    const int warp = tid >> 5;
    const int lane = tid & 31;
    const int row0 = (blockIdx.x * 8 + warp) * 16;
    const float4* t4 = reinterpret_cast<const float4*>(s_t);

    for (int rr = 0; rr < 16; rr++) {
        const int row = row0 + rr;
        const float4* p4 = reinterpret_cast<const float4*>(Qw + (size_t)row * RW);
        float acc = 0.0f;
#pragma unroll
        for (int u = 0; u < 4; u++) {
            float4 q = p4[lane + 32 * u];
            float4 tt = t4[lane + 32 * u];
            acc += q.x * tt.x + q.y * tt.y + q.z * tt.z + q.w * tt.w;
        }
#pragma unroll
        for (int off = 16; off > 0; off >>= 1)
            acc += __shfl_xor_sync(0xffffffffu, acc, off);
        if (lane == 0) {
            const __nv_bfloat16 hb = __float2bfloat16_rn(acc);
            g_Wph[row] = hb;
            g_Wpl[row] = __float2bfloat16_rn(acc - __bfloat162float(hb));
        }
    }
}

// ---------------------------------------------------------------------------
// K3: lin = x @ Wp^T + bp via bf16 3-way-split tensor mma + ldmatrix + cp.async.
// Block 256 thr = 8 warps (4m x 2n); block tile 128x64; warp tile 32x32.
// KP=20 -> 80B row stride (ldmatrix-aligned, conflict-free).
// Staging via cp.async.cg 16B (6 ops/thread/kt, replaces LDG+STS round-trip).
// grid (10, 32) = 320 blocks. LAUNCH #4 -> profiled.
// ---------------------------------------------------------------------------
#define KP 20   // u32 words per smem row (16 + 4 pad); row stride 80 B

__device__ __forceinline__ void mma_bf16(float* d, const unsigned* a,
                                         const unsigned* bq) {
    asm volatile(
        "mma.sync.aligned.m16n8k16.row.col.f32.bf16.bf16.f32 "
        "{%0,%1,%2,%3}, {%4,%5,%6,%7}, {%8,%9}, {%0,%1,%2,%3};"
        : "+f"(d[0]), "+f"(d[1]), "+f"(d[2]), "+f"(d[3])
        : "r"(a[0]), "r"(a[1]), "r"(a[2]), "r"(a[3]), "r"(bq[0]), "r"(bq[1]));
}

__device__ __forceinline__ void ldsm_x4(unsigned* r, unsigned addr) {
    asm volatile(
        "ldmatrix.sync.aligned.m8n8.x4.shared.b16 {%0,%1,%2,%3}, [%4];"
        : "=r"(r[0]), "=r"(r[1]), "=r"(r[2]), "=r"(r[3]) : "r"(addr));
}

__device__ __forceinline__ unsigned smem_u32(const void* p) {
    unsigned a;
    asm("{ .reg .u64 t; cvta.to.shared.u64 t, %1; cvt.u32.u64 %0, t; }"
        : "=r"(a) : "l"(p));
    return a;
}

__device__ __forceinline__ void cp16(unsigned dst, const void* src) {
    asm volatile("cp.async.cg.shared.global [%0], [%1], 16;"
                 :: "r"(dst), "l"(src));
}

__global__ __launch_bounds__(256) void k3_mma(void) {
    __shared__ unsigned Ah[128][KP];
    __shared__ unsigned Al[128][KP];
    __shared__ unsigned Bh[64][KP];
    __shared__ unsigned Bl[64][KP];

    const int tid  = threadIdx.x;
    const int warp = tid >> 5;
    const int lane = tid & 31;
    const int grp  = lane >> 2;
    const int tg   = lane & 3;
    const int wm = (warp >> 1) * 32;      // warp m offset within 128
    const int wn = (warp & 1) * 32;       // warp n offset within 64
    const int bn0 = blockIdx.x * 64;
    const int bm0 = blockIdx.y * 128;

    // ldmatrix lane-address components (same every kt; s adds 32 B)
    const int aRow = wm + (lane & 15);
    const int aCq  = (lane >> 4) * 4;
    const int bRow = wn + (lane & 7) + (lane >> 4) * 8;
    const int bCq  = ((lane >> 3) & 1) * 4;

    const unsigned ahA0 = smem_u32(&Ah[aRow][aCq]);
    const unsigned alA0 = smem_u32(&Al[aRow][aCq]);
    const unsigned bhA0 = smem_u32(&Bh[bRow][bCq]);
    const unsigned blA0 = smem_u32(&Bl[bRow][bCq]);

    float d[2][4][4];
#pragma unroll
    for (int mf = 0; mf < 2; mf++)
#pragma unroll
        for (int nf = 0; nf < 4; nf++)
#pragma unroll
            for (int q = 0; q < 4; q++) d[mf][nf][q] = 0.0f;

    // cp.async staging addresses (smem fixed; gmem advances 64 B per kt)
    const int ar0 = tid >> 2,          as0 = tid & 3;           // A chunk 0
    const int ar1 = (tid + 256) >> 2,  as1 = tid & 3;           // A chunk 1
    const int brw = tid >> 2,          bsg = tid & 3;           // B chunk
    const unsigned dAh0 = smem_u32(&Ah[ar0][as0 * 4]);
    const unsigned dAh1 = smem_u32(&Ah[ar1][as1 * 4]);
    const unsigned dAl0 = smem_u32(&Al[ar0][as0 * 4]);
    const unsigned dAl1 = smem_u32(&Al[ar1][as1 * 4]);
    const unsigned dBh  = smem_u32(&Bh[brw][bsg * 4]);
    const unsigned dBl  = smem_u32(&Bl[brw][bsg * 4]);
    const __nv_bfloat16* sAh0 = g_xh  + (size_t)(bm0 + ar0) * NIN + as0 * 8;
    const __nv_bfloat16* sAh1 = g_xh  + (size_t)(bm0 + ar1) * NIN + as1 * 8;
    const __nv_bfloat16* sAl0 = g_xl  + (size_t)(bm0 + ar0) * NIN + as0 * 8;
    const __nv_bfloat16* sAl1 = g_xl  + (size_t)(bm0 + ar1) * NIN + as1 * 8;
    const __nv_bfloat16* sBh  = g_Wph + (size_t)(bn0 + brw) * NIN + bsg * 8;
    const __nv_bfloat16* sBl  = g_Wpl + (size_t)(bn0 + brw) * NIN + bsg * 8;

    for (int kt = 0; kt < 16; kt++) {
        const int ko = kt * 32;   // bf16 elements
        cp16(dAh0, sAh0 + ko);
        cp16(dAh1, sAh1 + ko);
        cp16(dAl0, sAl0 + ko);
        cp16(dAl1, sAl1 + ko);
        cp16(dBh,  sBh  + ko);
        cp16(dBl,  sBl  + ko);
        asm volatile("cp.async.commit_group;");
        asm volatile("cp.async.wait_group 0;");
        __syncthreads();

#pragma unroll
        for (int s = 0; s < 2; s++) {
            const unsigned so = s * 32;   // +8 u32 cols = 32 B
            unsigned ah[2][4], al[2][4], bh[2][4], bl[2][4];
            ldsm_x4(ah[0], ahA0 + so);
            ldsm_x4(ah[1], ahA0 + so + 16 * (KP * 4));
            ldsm_x4(al[0], alA0 + so);
            ldsm_x4(al[1], alA0 + so + 16 * (KP * 4));
            ldsm_x4(bh[0], bhA0 + so);
            ldsm_x4(bh[1], bhA0 + so + 16 * (KP * 4));
            ldsm_x4(bl[0], blA0 + so);
            ldsm_x4(bl[1], blA0 + so + 16 * (KP * 4));
#pragma unroll
            for (int mf = 0; mf < 2; mf++)
#pragma unroll
                for (int p = 0; p < 2; p++) {
                    mma_bf16(d[mf][p * 2 + 0], ah[mf], &bh[p][0]);
                    mma_bf16(d[mf][p * 2 + 0], ah[mf], &bl[p][0]);
                    mma_bf16(d[mf][p * 2 + 0], al[mf], &bh[p][0]);
                    mma_bf16(d[mf][p * 2 + 1], ah[mf], &bh[p][2]);
                    mma_bf16(d[mf][p * 2 + 1], ah[mf], &bl[p][2]);
                    mma_bf16(d[mf][p * 2 + 1], al[mf], &bh[p][2]);
                }
        }
        __syncthreads();
    }

    // epilogue: add bias, store float2 per fragment half
#pragma unroll
    for (int nf = 0; nf < 4; nf++) {
        const int col = bn0 + wn + nf * 8 + tg * 2;
        const float2 bv = *reinterpret_cast<const float2*>(&g_bp[col]);
#pragma unroll
        for (int mf = 0; mf < 2; mf++) {
            const int row0 = bm0 + wm + mf * 16 + grp;
            float2 v0 = make_float2(d[mf][nf][0] + bv.x, d[mf][nf][1] + bv.y);
            float2 v1 = make_float2(d[mf][nf][2] + bv.x, d[mf][nf][3] + bv.y);
            *reinterpret_cast<float2*>(g_lin + (size_t)row0 * NOUT + col) = v0;
            *reinterpret_cast<float2*>(g_lin + (size_t)(row0 + 8) * NOUT + col) = v1;
        }
    }
}

// ---------------------------------------------------------------------------
// K4a: bilinear CSR -> preact (round-13 uint2 form — measured best)
// ---------------------------------------------------------------------------
extern __shared__ float2 k4_s2[];   // [640][33]

__global__ __launch_bounds__(512) void k4a_bilinear(void) {
    const int tid  = threadIdx.x;
    const int warp = tid >> 5;
    const int lane = tid & 31;
    const int grp  = blockIdx.x >> 1;
    const int half = blockIdx.x & 1;
    const int b0   = grp * 64;

#pragma unroll
    for (int i = 0; i < 4; i++) {
        const int bb = warp + 16 * i;
        const float* src = g_lin + (size_t)(b0 + bb) * NOUT;
        float* base = reinterpret_cast<float*>(k4_s2) + (bb & 1);
        const int pr = bb >> 1;
        for (int ch = lane; ch < NOUT; ch += 32)
            base[(ch * K4_P + pr) * 2] = src[ch];
    }
    __syncthreads();

    const unsigned long long* s_u64 =
        reinterpret_cast<const unsigned long long*>(k4_s2) + lane;
    unsigned long long c01;
    asm("mov.b64 %0, {%1, %1};" : "=l"(c01) : "f"(0.1f));

#define K4_STEP(ACC, PR)                                                      \
    {                                                                         \
        unsigned long long av = s_u64[((PR).x & 1023) * K4_P];                \
        unsigned long long bv = s_u64[(((PR).x >> 10) & 1023) * K4_P];        \
        const float pf = __uint_as_float((PR).y);                             \
        unsigned long long pp, t;                                             \
        asm("mov.b64 %0, {%1, %1};" : "=l"(pp) : "f"(pf));                    \
        asm("mul.rn.f32x2 %0, %1, %2;" : "=l"(t) : "l"(av), "l"(bv));         \
        asm("fma.rn.f32x2 %0, %1, %2, %0;" : "+l"(ACC) : "l"(t), "l"(pp));    \
    }

#pragma unroll 2
    for (int i = 0; i < 20; i++) {
        const int row = half * 320 + warp + 16 * i;
        const int ks = g_row_start[row];
        const int ke = g_row_start[row + 1];
        unsigned long long a0 = 0ull, a1 = 0ull, a2c = 0ull, a3 = 0ull;
        int k = ks;
        for (; k + 3 < ke; k += 4) {
            const uint2 p0 = g_pair[k + 0];
            const uint2 p1 = g_pair[k + 1];
            const uint2 p2 = g_pair[k + 2];
            const uint2 p3 = g_pair[k + 3];
            K4_STEP(a0, p0)
            K4_STEP(a1, p1)
            K4_STEP(a2c, p2)
            K4_STEP(a3, p3)
        }
        for (; k < ke; k++) {
            const uint2 p0 = g_pair[k];
            K4_STEP(a0, p0)
        }
        unsigned long long acc;
        asm("add.rn.f32x2 %0, %1, %2;" : "=l"(acc) : "l"(a0), "l"(a1));
        asm("add.rn.f32x2 %0, %1, %2;" : "+l"(acc) : "l"(acc), "l"(a2c));
        asm("add.rn.f32x2 %0, %1, %2;" : "+l"(acc) : "l"(acc), "l"(a3));

        unsigned long long linv = s_u64[row * K4_P];
        unsigned long long pv;
        asm("mul.rn.f32x2 %0, %1, %2;" : "=l"(pv) : "l"(acc), "l"(c01));
        asm("add.rn.f32x2 %0, %1, %2;" : "+l"(pv) : "l"(pv), "l"(linv));
        *reinterpret_cast<unsigned long long*>(
            g_pre + (size_t)row * BATCH + b0 + 2 * lane) = pv;
    }
}

// ---------------------------------------------------------------------------
// K4b: gated nonlinearity from transposed preact (FROZEN, ~6us)
// ---------------------------------------------------------------------------
__global__ __launch_bounds__(256) void k4b_gate(
    const int* __restrict__ gate_idx, float* __restrict__ out) {
    __shared__ float s_t[32][257];
    const int tid = threadIdx.x;
    const int b0 = blockIdx.x * 256;
    const int j0 = blockIdx.y * 32;

#pragma unroll 4
    for (int jj = 0; jj < 32; jj++) {
        const int j = j0 + jj;
        const int gi = gate_idx[j];
        const float v = g_pre[(size_t)j * BATCH + b0 + tid];
        const float g = g_pre[(size_t)gi * BATCH + b0 + tid];
        s_t[jj][tid] = v / (1.0f + __expf(-g));
    }
    __syncthreads();

    float* dst = out + (size_t)(b0 + tid) * NREP + j0;
#pragma unroll
    for (int q = 0; q < 8; q++) {
        float4 v = make_float4(s_t[q * 4 + 0][tid], s_t[q * 4 + 1][tid],
                               s_t[q * 4 + 2][tid], s_t[q * 4 + 3][tid]);
        *reinterpret_cast<float4*>(dst + q * 4) = v;
    }
}

// ---------------------------------------------------------------------------
// Launch
// ---------------------------------------------------------------------------
extern "C" void kernel_launch(void* const* d_in, const int* in_sizes, int n_in,
                              void* d_out, int out_size) {
    const float* x        = (const float*)d_in[0];
    const float* W_weight = (const float*)d_in[1];
    const float* b        = (const float*)d_in[2];
    const float* Qw       = (const float*)d_in[3];
    const float* Qb       = (const float*)d_in[4];
    const float* bi_p     = (const float*)d_in[5];
    const int*   bi_src   = (const int*)d_in[6];
    const int*   bi_row   = (const int*)d_in[7];
    const int*   bi_col   = (const int*)d_in[8];
    const int*   gate_idx = (const int*)d_in[9];
    float* out = (float*)d_out;

    static int smem_set = 0;
    const int k4_smem_bytes = NOUT * K4_P * sizeof(float2);  // 168,960
    if (!smem_set) {
        cudaFuncSetAttribute(k4a_bilinear,
                             cudaFuncAttributeMaxDynamicSharedMemorySize,
                             k4_smem_bytes);
        smem_set = 1;
    }

    kz<<<1, 512>>>();
    k1_qwt<<<1312, 512>>>(Qw, W_weight, x);   // 1280 GEMV + 32 x-split blocks
    k2_wp<<<2562, 256>>>(Qw, bi_src, bi_row, bi_col, bi_p, Qb, b);
    k3_mma<<<dim3(NOUT / 64, BATCH / 128), 256>>>();   // launch #4 -> profiled
    k4a_bilinear<<<128, 512, k4_smem_bytes>>>();
    k4b_gate<<<dim3(BATCH / 256, NREP / 32), 256>>>(gate_idx, out);
}

// round 17
// speedup vs baseline: 1.0638x; 1.0111x over previous
#include <cuda_runtime.h>
#include <cuda_bf16.h>
#include <math.h>

#define BATCH 4096
#define NIN   512
#define NREP  512
#define NOUT  640
#define RW    512
#define RB    64
#define NNZ   16384

// Scratch (static device globals — allowed)
__device__ float g_t[RW];
__device__ float g_bp[NOUT];
__device__ float g_lin[BATCH * NOUT];            // lin (+bias)
__device__ float g_pre[NOUT * BATCH];            // preact, TRANSPOSED [ch][batch]
__device__ uint2 g_pair[NNZ];                    // (src | col<<10, bits(param))
__device__ int   g_row_start[NOUT + 1];
__device__ __nv_bfloat16 g_xh[BATCH * NIN];      // x hi/lo split
__device__ __nv_bfloat16 g_xl[BATCH * NIN];
__device__ __nv_bfloat16 g_Wph[NOUT * NIN];      // Wp hi/lo split
__device__ __nv_bfloat16 g_Wpl[NOUT * NIN];

#define K4_P 33   // f32x2 words per channel row in k4a smem

// ---------------------------------------------------------------------------
// K0: zero g_t (also keeps k3 at launch slot 4 -> ncu profiles it)
// ---------------------------------------------------------------------------
__global__ void kz(void) { g_t[threadIdx.x] = 0.0f; }

// ---------------------------------------------------------------------------
// K1: t = Qw^T @ wflat (blocks 0..1279, at DRAM roofline — FROZEN)
// Blocks 1280..1311: x -> bf16 hi/lo split (rides free under the Qw stream).
// ---------------------------------------------------------------------------
__global__ __launch_bounds__(512) void k1_qwt(const float* __restrict__ Qw,
                                              const float* __restrict__ w,
                                              const float* __restrict__ x) {
    const int tid = threadIdx.x;
    if (blockIdx.x >= 1280) {
        const int cb = blockIdx.x - 1280;                 // 0..31
        const float4* x4 = reinterpret_cast<const float4*>(x);
        uint2* xh2 = reinterpret_cast<uint2*>(g_xh);
        uint2* xl2 = reinterpret_cast<uint2*>(g_xl);
#pragma unroll 4
        for (int i = 0; i < 32; i++) {
            const int idx4 = cb * 16384 + i * 512 + tid;  // float4 index
            const float4 v = x4[idx4];
            __nv_bfloat16 h0 = __float2bfloat16_rn(v.x);
            __nv_bfloat16 h1 = __float2bfloat16_rn(v.y);
            __nv_bfloat16 h2 = __float2bfloat16_rn(v.z);
            __nv_bfloat16 h3 = __float2bfloat16_rn(v.w);
            __nv_bfloat16 l0 = __float2bfloat16_rn(v.x - __bfloat162float(h0));
            __nv_bfloat16 l1 = __float2bfloat16_rn(v.y - __bfloat162float(h1));
            __nv_bfloat16 l2 = __float2bfloat16_rn(v.z - __bfloat162float(h2));
            __nv_bfloat16 l3 = __float2bfloat16_rn(v.w - __bfloat162float(h3));
            uint2 uh, ul;
            uh.x = ((unsigned)__bfloat16_as_ushort(h1) << 16) | __bfloat16_as_ushort(h0);
            uh.y = ((unsigned)__bfloat16_as_ushort(h3) << 16) | __bfloat16_as_ushort(h2);
            ul.x = ((unsigned)__bfloat16_as_ushort(l1) << 16) | __bfloat16_as_ushort(l0);
            ul.y = ((unsigned)__bfloat16_as_ushort(l3) << 16) | __bfloat16_as_ushort(l2);
            xh2[idx4] = uh;
            xl2[idx4] = ul;
        }
        return;
    }

    __shared__ float s_w[256];
    const int rowBase = blockIdx.x * 256;
    if (tid < 256) s_w[tid] = w[rowBase + tid];
    __syncthreads();

    float acc = 0.0f;
    const float* p = Qw + (size_t)rowBase * RW + tid;
#pragma unroll 8
    for (int i = 0; i < 256; i++) {
        acc += p[(size_t)i * RW] * s_w[i];
    }
    atomicAdd(&g_t[tid], acc);
}

// ---------------------------------------------------------------------------
// K2: Wp[i] = dot(Qw[i,:], t), written as bf16 hi/lo (second Qw stream).
// Blocks 0..2559: GEMV. Block 2560: CSR sort. Block 2561: bias.
// ---------------------------------------------------------------------------
__global__ __launch_bounds__(256) void k2_wp(
    const float* __restrict__ Qw,
    const int* __restrict__ bsrc, const int* __restrict__ brow,
    const int* __restrict__ bcol, const float* __restrict__ bp_params,
    const float* __restrict__ Qb, const float* __restrict__ b) {
    const int tid = threadIdx.x;

    if (blockIdx.x >= 2560) {
        if (blockIdx.x == 2560) {
            __shared__ int c[NOUT];
            __shared__ int scan[NOUT];
            __shared__ int off[NOUT];
            for (int i = tid; i < NOUT; i += 256) c[i] = 0;
            __syncthreads();
            for (int k = tid; k < NNZ; k += 256) atomicAdd(&c[brow[k]], 1);
            __syncthreads();
            if (tid < 32) {
                int base = 0;
#pragma unroll
                for (int ch = 0; ch < NOUT / 32; ch++) {
                    int v = c[ch * 32 + tid];
#pragma unroll
                    for (int d = 1; d < 32; d <<= 1) {
                        int n = __shfl_up_sync(0xffffffffu, v, d);
                        if (tid >= d) v += n;
                    }
                    scan[ch * 32 + tid] = v + base;
                    base += __shfl_sync(0xffffffffu, v, 31);
                }
            }
            __syncthreads();
            for (int i = tid; i < NOUT; i += 256) {
                const int s = scan[i] - c[i];
                g_row_start[i] = s;
                off[i] = s;
            }
            if (tid == 0) g_row_start[NOUT] = NNZ;
            __syncthreads();
            for (int k = tid; k < NNZ; k += 256) {
                const int r = brow[k];
                const int pos = atomicAdd(&off[r], 1);
                g_pair[pos] = make_uint2(
                    (unsigned)bsrc[k] | ((unsigned)bcol[k] << 10),
                    __float_as_uint(bp_params[k]));
            }
        } else {
            __shared__ float s_part[4][RB];
            __shared__ float s_s[RB];
            const int r = tid & 63;
            const int chunk = tid >> 6;
            float acc = 0.0f;
            for (int i = chunk * 160; i < chunk * 160 + 160; i++)
                acc += Qb[i * RB + r] * b[i];
            s_part[chunk][r] = acc;
            __syncthreads();
            if (tid < RB) {
                s_s[tid] = s_part[0][tid] + s_part[1][tid] +
                           s_part[2][tid] + s_part[3][tid];
            }
            __syncthreads();
            for (int j = tid; j < NOUT; j += 256) {
                const float4* q4 = reinterpret_cast<const float4*>(Qb + j * RB);
                const float4* s4 = reinterpret_cast<const float4*>(s_s);
                float a = 0.0f;
#pragma unroll
                for (int u = 0; u < 16; u++) {
                    float4 q = q4[u];
                    float4 s = s4[u];
                    a += q.x * s.x + q.y * s.y + q.z * s.z + q.w * s.w;
                }
                g_bp[j] = a;
            }
        }
        return;
    }

    __shared__ float s_t[RW];
    for (int i = tid; i < RW; i += 256) s_t[i] = g_t[i];
    __syncthreads();

    const int warp = tid >> 5;
    const int lane = tid & 31;
    const int row0 = (blockIdx.x * 8 + warp) * 16;
    const float4* t4 = reinterpret_cast<const float4*>(s_t);

    for (int rr = 0; rr < 16; rr++) {
        const int row = row0 + rr;
        const float4* p4 = reinterpret_cast<const float4*>(Qw + (size_t)row * RW);
        float acc = 0.0f;
#pragma unroll
        for (int u = 0; u < 4; u++) {
            float4 q = p4[lane + 32 * u];
            float4 tt = t4[lane + 32 * u];
            acc += q.x * tt.x + q.y * tt.y + q.z * tt.z + q.w * tt.w;
        }
#pragma unroll
        for (int off = 16; off > 0; off >>= 1)
            acc += __shfl_xor_sync(0xffffffffu, acc, off);
        if (lane == 0) {
            const __nv_bfloat16 hb = __float2bfloat16_rn(acc);
            g_Wph[row] = hb;
            g_Wpl[row] = __float2bfloat16_rn(acc - __bfloat162float(hb));
        }
    }
}

// ---------------------------------------------------------------------------
// K3: lin = x @ Wp^T + bp via bf16 3-way-split tensor mma + ldmatrix +
// DOUBLE-BUFFERED cp.async (copy of tile kt+1 overlaps compute of tile kt).
// Block 256 thr = 8 warps (4m x 2n); block tile 128x64; warp tile 32x32.
// KP=20 -> 80B row stride (ldmatrix-aligned, conflict-free).
// grid (10, 32) = 320 blocks. LAUNCH #4 -> profiled.
// ---------------------------------------------------------------------------
#define KP 20   // u32 words per smem row (16 + 4 pad); row stride 80 B
#define A_BUF_B (128 * KP * 4)   // bytes per A buffer
#define B_BUF_B (64 * KP * 4)    // bytes per B buffer

__device__ __forceinline__ void mma_bf16(float* d, const unsigned* a,
                                         const unsigned* bq) {
    asm volatile(
        "mma.sync.aligned.m16n8k16.row.col.f32.bf16.bf16.f32 "
        "{%0,%1,%2,%3}, {%4,%5,%6,%7}, {%8,%9}, {%0,%1,%2,%3};"
        : "+f"(d[0]), "+f"(d[1]), "+f"(d[2]), "+f"(d[3])
        : "r"(a[0]), "r"(a[1]), "r"(a[2]), "r"(a[3]), "r"(bq[0]), "r"(bq[1]));
}

__device__ __forceinline__ void ldsm_x4(unsigned* r, unsigned addr) {
    asm volatile(
        "ldmatrix.sync.aligned.m8n8.x4.shared.b16 {%0,%1,%2,%3}, [%4];"
        : "=r"(r[0]), "=r"(r[1]), "=r"(r[2]), "=r"(r[3]) : "r"(addr));
}

__device__ __forceinline__ unsigned smem_u32(const void* p) {
    unsigned a;
    asm("{ .reg .u64 t; cvta.to.shared.u64 t, %1; cvt.u32.u64 %0, t; }"
        : "=r"(a) : "l"(p));
    return a;
}

__device__ __forceinline__ void cp16(unsigned dst, const void* src) {
    asm volatile("cp.async.cg.shared.global [%0], [%1], 16;"
                 :: "r"(dst), "l"(src));
}

__global__ __launch_bounds__(256) void k3_mma(void) {
    __shared__ unsigned Ah[2][128][KP];
    __shared__ unsigned Al[2][128][KP];
    __shared__ unsigned Bh[2][64][KP];
    __shared__ unsigned Bl[2][64][KP];

    const int tid  = threadIdx.x;
    const int warp = tid >> 5;
    const int lane = tid & 31;
    const int grp  = lane >> 2;
    const int tg   = lane & 3;
    const int wm = (warp >> 1) * 32;      // warp m offset within 128
    const int wn = (warp & 1) * 32;       // warp n offset within 64
    const int bn0 = blockIdx.x * 64;
    const int bm0 = blockIdx.y * 128;

    // ldmatrix lane-address components for buffer 0
    const int aRow = wm + (lane & 15);
    const int aCq  = (lane >> 4) * 4;
    const int bRow = wn + (lane & 7) + (lane >> 4) * 8;
    const int bCq  = ((lane >> 3) & 1) * 4;

    const unsigned ahA0 = smem_u32(&Ah[0][aRow][aCq]);
    const unsigned alA0 = smem_u32(&Al[0][aRow][aCq]);
    const unsigned bhA0 = smem_u32(&Bh[0][bRow][bCq]);
    const unsigned blA0 = smem_u32(&Bl[0][bRow][bCq]);

    float d[2][4][4];
#pragma unroll
    for (int mf = 0; mf < 2; mf++)
#pragma unroll
        for (int nf = 0; nf < 4; nf++)
#pragma unroll
            for (int q = 0; q < 4; q++) d[mf][nf][q] = 0.0f;

    // cp.async staging (buffer 0 addresses; add buf offset per iteration)
    const int ar0 = tid >> 2,          as0 = tid & 3;
    const int ar1 = (tid + 256) >> 2,  as1 = tid & 3;
    const int brw = tid >> 2,          bsg = tid & 3;
    const unsigned dAh0 = smem_u32(&Ah[0][ar0][as0 * 4]);
    const unsigned dAh1 = smem_u32(&Ah[0][ar1][as1 * 4]);
    const unsigned dAl0 = smem_u32(&Al[0][ar0][as0 * 4]);
    const unsigned dAl1 = smem_u32(&Al[0][ar1][as1 * 4]);
    const unsigned dBh  = smem_u32(&Bh[0][brw][bsg * 4]);
    const unsigned dBl  = smem_u32(&Bl[0][brw][bsg * 4]);
    const __nv_bfloat16* sAh0 = g_xh  + (size_t)(bm0 + ar0) * NIN + as0 * 8;
    const __nv_bfloat16* sAh1 = g_xh  + (size_t)(bm0 + ar1) * NIN + as1 * 8;
    const __nv_bfloat16* sAl0 = g_xl  + (size_t)(bm0 + ar0) * NIN + as0 * 8;
    const __nv_bfloat16* sAl1 = g_xl  + (size_t)(bm0 + ar1) * NIN + as1 * 8;
    const __nv_bfloat16* sBh  = g_Wph + (size_t)(bn0 + brw) * NIN + bsg * 8;
    const __nv_bfloat16* sBl  = g_Wpl + (size_t)(bn0 + brw) * NIN + bsg * 8;

    // prologue: stage tile 0 into buffer 0
    cp16(dAh0, sAh0); cp16(dAh1, sAh1);
    cp16(dAl0, sAl0); cp16(dAl1, sAl1);
    cp16(dBh,  sBh);  cp16(dBl,  sBl);
    asm volatile("cp.async.commit_group;");

    for (int kt = 0; kt < 16; kt++) {
        const int cbuf = kt & 1;
        if (kt < 15) {
            // prefetch tile kt+1 into the other buffer (overlaps compute)
            const unsigned nb = ((kt + 1) & 1);
            const unsigned aOff = nb * A_BUF_B;
            const unsigned bOff = nb * B_BUF_B;
            const int ko = (kt + 1) * 32;
            cp16(dAh0 + aOff, sAh0 + ko);
            cp16(dAh1 + aOff, sAh1 + ko);
            cp16(dAl0 + aOff, sAl0 + ko);
            cp16(dAl1 + aOff, sAl1 + ko);
            cp16(dBh  + bOff, sBh  + ko);
            cp16(dBl  + bOff, sBl  + ko);
            asm volatile("cp.async.commit_group;");
            asm volatile("cp.async.wait_group 1;");
        } else {
            asm volatile("cp.async.wait_group 0;");
        }
        __syncthreads();

        const unsigned aOffC = cbuf * A_BUF_B;
        const unsigned bOffC = cbuf * B_BUF_B;
#pragma unroll
        for (int s = 0; s < 2; s++) {
            const unsigned so = s * 32;   // +8 u32 cols = 32 B
            unsigned ah[2][4], al[2][4], bh[2][4], bl[2][4];
            ldsm_x4(ah[0], ahA0 + aOffC + so);
            ldsm_x4(ah[1], ahA0 + aOffC + so + 16 * (KP * 4));
            ldsm_x4(al[0], alA0 + aOffC + so);
            ldsm_x4(al[1], alA0 + aOffC + so + 16 * (KP * 4));
            ldsm_x4(bh[0], bhA0 + bOffC + so);
            ldsm_x4(bh[1], bhA0 + bOffC + so + 16 * (KP * 4));
            ldsm_x4(bl[0], blA0 + bOffC + so);
            ldsm_x4(bl[1], blA0 + bOffC + so + 16 * (KP * 4));
#pragma unroll
            for (int mf = 0; mf < 2; mf++)
#pragma unroll
                for (int p = 0; p < 2; p++) {
                    mma_bf16(d[mf][p * 2 + 0], ah[mf], &bh[p][0]);
                    mma_bf16(d[mf][p * 2 + 0], ah[mf], &bl[p][0]);
                    mma_bf16(d[mf][p * 2 + 0], al[mf], &bh[p][0]);
                    mma_bf16(d[mf][p * 2 + 1], ah[mf], &bh[p][2]);
                    mma_bf16(d[mf][p * 2 + 1], ah[mf], &bl[p][2]);
                    mma_bf16(d[mf][p * 2 + 1], al[mf], &bh[p][2]);
                }
        }
        __syncthreads();   // protect buffer cbuf before kt+1's prefetch reuses it
    }

    // epilogue: add bias, store float2 per fragment half
#pragma unroll
    for (int nf = 0; nf < 4; nf++) {
        const int col = bn0 + wn + nf * 8 + tg * 2;
        const float2 bv = *reinterpret_cast<const float2*>(&g_bp[col]);
#pragma unroll
        for (int mf = 0; mf < 2; mf++) {
            const int row0 = bm0 + wm + mf * 16 + grp;
            float2 v0 = make_float2(d[mf][nf][0] + bv.x, d[mf][nf][1] + bv.y);
            float2 v1 = make_float2(d[mf][nf][2] + bv.x, d[mf][nf][3] + bv.y);
            *reinterpret_cast<float2*>(g_lin + (size_t)row0 * NOUT + col) = v0;
            *reinterpret_cast<float2*>(g_lin + (size_t)(row0 + 8) * NOUT + col) = v1;
        }
    }
}

// ---------------------------------------------------------------------------
// K4a: bilinear CSR -> preact (round-13 uint2 form — measured best)
// ---------------------------------------------------------------------------
extern __shared__ float2 k4_s2[];   // [640][33]

__global__ __launch_bounds__(512) void k4a_bilinear(void) {
    const int tid  = threadIdx.x;
    const int warp = tid >> 5;
    const int lane = tid & 31;
    const int grp  = blockIdx.x >> 1;
    const int half = blockIdx.x & 1;
    const int b0   = grp * 64;

#pragma unroll
    for (int i = 0; i < 4; i++) {
        const int bb = warp + 16 * i;
        const float* src = g_lin + (size_t)(b0 + bb) * NOUT;
        float* base = reinterpret_cast<float*>(k4_s2) + (bb & 1);
        const int pr = bb >> 1;
        for (int ch = lane; ch < NOUT; ch += 32)
            base[(ch * K4_P + pr) * 2] = src[ch];
    }
    __syncthreads();

    const unsigned long long* s_u64 =
        reinterpret_cast<const unsigned long long*>(k4_s2) + lane;
    unsigned long long c01;
    asm("mov.b64 %0, {%1, %1};" : "=l"(c01) : "f"(0.1f));

#define K4_STEP(ACC, PR)                                                      \
    {                                                                         \
        unsigned long long av = s_u64[((PR).x & 1023) * K4_P];                \
        unsigned long long bv = s_u64[(((PR).x >> 10) & 1023) * K4_P];        \
        const float pf = __uint_as_float((PR).y);                             \
        unsigned long long pp, t;                                             \
        asm("mov.b64 %0, {%1, %1};" : "=l"(pp) : "f"(pf));                    \
        asm("mul.rn.f32x2 %0, %1, %2;" : "=l"(t) : "l"(av), "l"(bv));         \
        asm("fma.rn.f32x2 %0, %1, %2, %0;" : "+l"(ACC) : "l"(t), "l"(pp));    \
    }

#pragma unroll 2
    for (int i = 0; i < 20; i++) {
        const int row = half * 320 + warp + 16 * i;
        const int ks = g_row_start[row];
        const int ke = g_row_start[row + 1];
        unsigned long long a0 = 0ull, a1 = 0ull, a2c = 0ull, a3 = 0ull;
        int k = ks;
        for (; k + 3 < ke; k += 4) {
            const uint2 p0 = g_pair[k + 0];
            const uint2 p1 = g_pair[k + 1];
            const uint2 p2 = g_pair[k + 2];
            const uint2 p3 = g_pair[k + 3];
            K4_STEP(a0, p0)
            K4_STEP(a1, p1)
            K4_STEP(a2c, p2)
            K4_STEP(a3, p3)
        }
        for (; k < ke; k++) {
            const uint2 p0 = g_pair[k];
            K4_STEP(a0, p0)
        }
        unsigned long long acc;
        asm("add.rn.f32x2 %0, %1, %2;" : "=l"(acc) : "l"(a0), "l"(a1));
        asm("add.rn.f32x2 %0, %1, %2;" : "+l"(acc) : "l"(acc), "l"(a2c));
        asm("add.rn.f32x2 %0, %1, %2;" : "+l"(acc) : "l"(acc), "l"(a3));

        unsigned long long linv = s_u64[row * K4_P];
        unsigned long long pv;
        asm("mul.rn.f32x2 %0, %1, %2;" : "=l"(pv) : "l"(acc), "l"(c01));
        asm("add.rn.f32x2 %0, %1, %2;" : "+l"(pv) : "l"(pv), "l"(linv));
        *reinterpret_cast<unsigned long long*>(
            g_pre + (size_t)row * BATCH + b0 + 2 * lane) = pv;
    }
}

// ---------------------------------------------------------------------------
// K4b: gated nonlinearity from transposed preact (FROZEN, ~6us)
// ---------------------------------------------------------------------------
__global__ __launch_bounds__(256) void k4b_gate(
    const int* __restrict__ gate_idx, float* __restrict__ out) {
    __shared__ float s_t[32][257];
    const int tid = threadIdx.x;
    const int b0 = blockIdx.x * 256;
    const int j0 = blockIdx.y * 32;

#pragma unroll 4
    for (int jj = 0; jj < 32; jj++) {
        const int j = j0 + jj;
        const int gi = gate_idx[j];
        const float v = g_pre[(size_t)j * BATCH + b0 + tid];
        const float g = g_pre[(size_t)gi * BATCH + b0 + tid];
        s_t[jj][tid] = v / (1.0f + __expf(-g));
    }
    __syncthreads();

    float* dst = out + (size_t)(b0 + tid) * NREP + j0;
#pragma unroll
    for (int q = 0; q < 8; q++) {
        float4 v = make_float4(s_t[q * 4 + 0][tid], s_t[q * 4 + 1][tid],
                               s_t[q * 4 + 2][tid], s_t[q * 4 + 3][tid]);
        *reinterpret_cast<float4*>(dst + q * 4) = v;
    }
}

// ---------------------------------------------------------------------------
// Launch
// ---------------------------------------------------------------------------
extern "C" void kernel_launch(void* const* d_in, const int* in_sizes, int n_in,
                              void* d_out, int out_size) {
    const float* x        = (const float*)d_in[0];
    const float* W_weight = (const float*)d_in[1];
    const float* b        = (const float*)d_in[2];
    const float* Qw       = (const float*)d_in[3];
    const float* Qb       = (const float*)d_in[4];
    const float* bi_p     = (const float*)d_in[5];
    const int*   bi_src   = (const int*)d_in[6];
    const int*   bi_row   = (const int*)d_in[7];
    const int*   bi_col   = (const int*)d_in[8];
    const int*   gate_idx = (const int*)d_in[9];
    float* out = (float*)d_out;

    static int smem_set = 0;
    const int k4_smem_bytes = NOUT * K4_P * sizeof(float2);  // 168,960
    if (!smem_set) {
        cudaFuncSetAttribute(k4a_bilinear,
                             cudaFuncAttributeMaxDynamicSharedMemorySize,
                             k4_smem_bytes);
        smem_set = 1;
    }

    kz<<<1, 512>>>();
    k1_qwt<<<1312, 512>>>(Qw, W_weight, x);   // 1280 GEMV + 32 x-split blocks
    k2_wp<<<2562, 256>>>(Qw, bi_src, bi_row, bi_col, bi_p, Qb, b);
    k3_mma<<<dim3(NOUT / 64, BATCH / 128), 256>>>();   // launch #4 -> profiled
    k4a_bilinear<<<128, 512, k4_smem_bytes>>>();
    k4b_gate<<<dim3(BATCH / 256, NREP / 32), 256>>>(gate_idx, out);
}